// round 14
// baseline (speedup 1.0000x reference)
#include <cuda_runtime.h>
#include <cuda_bf16.h>
#include <math.h>

#define TOKS 8192
#define ELEMS 1048576
typedef unsigned long long ull;
typedef unsigned int u32;
typedef unsigned short u16;

// ---------------- scratch ----------------
__device__ float g_h[ELEMS];        // ping-pong residual buffer
__device__ float g_a[ELEMS];        // attention output
__device__ float g_qkv[3*ELEMS];
__device__ u32 g_wB[10*16384];      // weights in mma.sync B-frag order, hi/lo split
__device__ u32 g_kvF[2*128*8192];   // K,V frags per (b,h)

// ---------------- helpers ----------------
__device__ __forceinline__ u16 bfhi(float v) {
    return __bfloat16_as_ushort(__float2bfloat16_rn(v));
}
__device__ __forceinline__ float bf2f(u16 u) {
    return __bfloat162float(__ushort_as_bfloat16(u));
}
__device__ __forceinline__ float ex2f(float x) {
    float r; asm("ex2.approx.f32 %0, %1;" : "=f"(r) : "f"(x)); return r;
}
__device__ __forceinline__ u32 cvtbf2(float hi, float lo) {
    u32 r; asm("cvt.rn.bf16x2.f32 %0, %1, %2;" : "=r"(r) : "f"(hi), "f"(lo)); return r;
}
__device__ __forceinline__ void mma16816(float4& c, const uint4& a, const uint2& b) {
    asm("mma.sync.aligned.m16n8k16.row.col.f32.bf16.bf16.f32 "
        "{%0,%1,%2,%3}, {%4,%5,%6,%7}, {%8,%9}, {%0,%1,%2,%3};"
        : "+f"(c.x), "+f"(c.y), "+f"(c.z), "+f"(c.w)
        : "r"(a.x), "r"(a.y), "r"(a.z), "r"(a.w), "r"(b.x), "r"(b.y));
}
__device__ __forceinline__ void split2(float f0, float f1, u32& hi, u32& lo) {
    hi = cvtbf2(f1, f0);
    float h0 = __uint_as_float(hi << 16);
    float h1 = __uint_as_float(hi & 0xFFFF0000u);
    lo = cvtbf2(f1 - h1, f0 - h0);
}
__device__ __forceinline__ void cpasync16(u32 saddr, const void* g) {
    asm volatile("cp.async.cg.shared.global [%0], [%1], 16;" :: "r"(saddr), "l"(g));
}

// ---------------- weight prep (R11 layout: B-frags hi @0, lo @+8192 u32) ----------------
__global__ void prep_weights(const float* __restrict__ Wq, const float* __restrict__ Wk,
                             const float* __restrict__ Wv, const float* __restrict__ pw,
                             const float* __restrict__ f1, const float* __restrict__ f2,
                             const float* __restrict__ Wo, u32* __restrict__ wB) {
    int idx = blockIdx.x*256 + threadIdx.x;          // 10*16384
    if (idx >= 10*16384) return;
    int j = idx >> 14, r = idx & 16383;
    int k = r >> 7, n = r & 127;
    float v;
    if (j < 3) {
        const float* W = (j==0) ? Wq : (j==1) ? Wk : Wv;   // (H,128,16)
        v = W[(n>>4)*2048 + k*16 + (n&15)];
    } else if (j < 7) {
        v = pw[(j-3)*16384 + n*128 + k];
    } else if (j < 9) {
        const float* W = (j==7) ? f1 : f2;
        v = W[n*128 + k];
    } else {
        v = Wo[k*128 + n];
    }
    u16 h = bfhi(v);
    u16 l = bfhi(v - bf2f(h));
    int kt = k >> 4, kk = k & 15;
    int reg = kk >> 3, tig = (kk & 7) >> 1, bb = kk & 1;
    int nt = n >> 3, lane = (n & 7)*4 + tig;
    u16* w16 = (u16*)(wB + (size_t)j*16384);
    int i32h = ((kt*16 + nt)*32 + lane)*2 + reg;
    int i32l = (((8 + kt)*16 + nt)*32 + lane)*2 + reg;
    w16[i32h*2 + bb] = h;
    w16[i32l*2 + bb] = l;
}

// ---------------- addpos: out = x + pos ----------------
__global__ __launch_bounds__(512) void addpos(const float* __restrict__ x,
                                              float* __restrict__ out) {
    int m0 = blockIdx.x * 64;
    int lane = threadIdx.x & 31, warp = threadIdx.x >> 5;
    int col = lane * 4;
    const float inc = 0.14619588050756158f;   // log(10000)/63
    #pragma unroll
    for (int i = 0; i < 4; i++) {
        int m = m0 + warp*4 + i;
        int s = m & 511;
        float4 xv = *(const float4*)&x[m*128 + col];
        float v[4] = {xv.x, xv.y, xv.z, xv.w};
        #pragma unroll
        for (int jj = 0; jj < 4; jj++) {
            int d = col + jj;
            int dd = d & 63;
            float a = (float)s * expf(-inc*(float)dd);
            v[jj] += (d < 64) ? sinf(a) : cosf(a);
        }
        float4 ov = {v[0], v[1], v[2], v[3]};
        *(float4*)&out[m*128 + col] = ov;
    }
}

// ============ gemmNT: M=32 tile, 256 thr; optional LN producer ============
// smem: B32 @0 (16384 u32), A32 @16384 (union Csm 32x132)
template<bool LNP, bool MULTI, int BIASM, bool RES>
__global__ __launch_bounds__(256) void gemmNT(
    const float* __restrict__ A, const u32* __restrict__ Wf,
    const float* __restrict__ bias, const float* __restrict__ res,
    float* __restrict__ out,
    const float* __restrict__ lnS, const float* __restrict__ lnB)
{
    extern __shared__ u32 smu[];
    u32* B32 = smu;
    u32* A32 = smu + 16384;
    float* Csm = (float*)(smu + 16384);
    if (MULTI) { Wf += blockIdx.y * 16384; out += (size_t)blockIdx.y * ELEMS; }

    int m0 = blockIdx.x * 32;
    int t = threadIdx.x, lane = t & 31, warp = t >> 5;

    {
        u32 sb = (u32)__cvta_generic_to_shared(&B32[t*4]);
        const u32* gs = Wf + t*4;
        #pragma unroll
        for (int i = 0; i < 16; i++)
            cpasync16(sb + i*4096, gs + i*1024);
        asm volatile("cp.async.commit_group;" ::: "memory");
    }

    // producer: warp owns rows 4w..4w+3; lane owns cols lane*4..+3
    {
        int k0 = lane*4;
        float4 g4 = {1,1,1,1}, b4 = {0,0,0,0};
        if (LNP) { g4 = *(const float4*)&lnS[k0]; b4 = *(const float4*)&lnB[k0]; }
        int kt = k0 >> 4;
        #pragma unroll
        for (int rr = 0; rr < 4; rr++) {
            int ml = warp*4 + rr;
            float4 v = *(const float4*)&A[(size_t)(m0 + ml)*128 + k0];
            float vv[4] = {v.x, v.y, v.z, v.w};
            if (LNP) {
                float s = vv[0]+vv[1]+vv[2]+vv[3];
                float q = vv[0]*vv[0]+vv[1]*vv[1]+vv[2]*vv[2]+vv[3]*vv[3];
                #pragma unroll
                for (int o = 16; o > 0; o >>= 1) {
                    s += __shfl_xor_sync(0xffffffffu, s, o);
                    q += __shfl_xor_sync(0xffffffffu, q, o);
                }
                float mu = s * (1.0f/128.0f);
                float var = q * (1.0f/128.0f) - mu*mu;
                float ri = rsqrtf(var + 1e-5f);
                vv[0] = (vv[0]-mu)*ri*g4.x + b4.x;
                vv[1] = (vv[1]-mu)*ri*g4.y + b4.y;
                vv[2] = (vv[2]-mu)*ri*g4.z + b4.z;
                vv[3] = (vv[3]-mu)*ri*g4.w + b4.w;
            }
            int mt = ml >> 4, mm = ml & 15;
            int g = mm & 7, hi8 = mm >> 3;
            #pragma unroll
            for (int j = 0; j < 4; j += 2) {
                int k = k0 + j;
                int tig = (k & 7) >> 1;
                int reg = hi8 + 2*((k & 15) >> 3);
                int ln2 = g*4 + tig;
                u32 hi, lo;
                split2(vv[j], vv[j+1], hi, lo);
                A32[((mt*8 + kt)*32 + ln2)*4 + reg]     = hi;
                A32[(((2+mt)*8 + kt)*32 + ln2)*4 + reg] = lo;
            }
        }
    }
    asm volatile("cp.async.wait_group 0;" ::: "memory");
    __syncthreads();

    int wm = warp >> 2, wn = warp & 3;
    int nt0 = wn*4;
    float4 acc[4];
    #pragma unroll
    for (int j = 0; j < 4; j++) acc[j] = make_float4(0.f,0.f,0.f,0.f);

    #pragma unroll
    for (int kt = 0; kt < 8; kt++) {
        uint4 ah = *(const uint4*)&A32[((wm*8 + kt)*32 + lane)*4];
        uint4 al = *(const uint4*)&A32[(((2+wm)*8 + kt)*32 + lane)*4];
        uint2 bh[4], bl[4];
        #pragma unroll
        for (int j = 0; j < 4; j++) {
            bh[j] = *(const uint2*)&B32[((kt*16 + nt0+j)*32 + lane)*2];
            bl[j] = *(const uint2*)&B32[(((8+kt)*16 + nt0+j)*32 + lane)*2];
        }
        #pragma unroll
        for (int j = 0; j < 4; j++) {
            mma16816(acc[j], ah, bh[j]);
            mma16816(acc[j], ah, bl[j]);
            mma16816(acc[j], al, bh[j]);
        }
    }
    __syncthreads();

    #pragma unroll
    for (int j = 0; j < 4; j++) {
        int row = wm*16 + (lane >> 2);
        int col = (nt0+j)*8 + (lane & 3)*2;
        float2 lo = {acc[j].x, acc[j].y};
        float2 hi = {acc[j].z, acc[j].w};
        *(float2*)&Csm[row*132 + col]     = lo;
        *(float2*)&Csm[(row+8)*132 + col] = hi;
    }
    __syncthreads();

    int colE = lane*4;
    float4 bv = {0,0,0,0};
    if (BIASM == 1) bv = *(const float4*)&bias[colE];
    float bs = (BIASM == 2) ? bias[0] : 0.f;

    #pragma unroll
    for (int i = 0; i < 4; i++) {
        int row = warp*4 + i;
        int m = m0 + row;
        float4 c4 = *(const float4*)&Csm[row*132 + colE];
        float v[4] = {c4.x, c4.y, c4.z, c4.w};
        #pragma unroll
        for (int jj = 0; jj < 4; jj++) {
            float val = v[jj];
            if (BIASM == 1) val += ((const float*)&bv)[jj];
            if (BIASM == 2) val += bs;
            v[jj] = val;
        }
        if (RES) {
            float4 r4 = *(const float4*)&res[(size_t)m*128 + colE];
            v[0] += r4.x; v[1] += r4.y; v[2] += r4.z; v[3] += r4.w;
        }
        float4 ov = {v[0], v[1], v[2], v[3]};
        *(float4*)&out[(size_t)m*128 + colE] = ov;
    }
}

// ============ gemmConvF: LN + depthwise-conv7 producer + pw GEMM ============
// smem: B32 @0 (16384), A32 @16384 (4224, union Csm), Raw @20608 (4864 f32),
//       Mu @25472 (64), Ri @25536 (64) => 25600 u32
__global__ __launch_bounds__(256) void gemmConvF(
    const float* __restrict__ A, const u32* __restrict__ Wf,
    const float* __restrict__ bias, float* __restrict__ out,
    const float* __restrict__ lnS, const float* __restrict__ lnB,
    const float* __restrict__ dww, const float* __restrict__ dwb)
{
    extern __shared__ u32 smu[];
    u32* B32 = smu;
    u32* A32 = smu + 16384;
    float* Csm = (float*)(smu + 16384);
    float* Raw = (float*)(smu + 20608);     // 38 rows x 128
    float* Mu  = (float*)(smu + 25472);
    float* Ri  = (float*)(smu + 25536);

    int m0 = blockIdx.x * 32;
    int t = threadIdx.x, lane = t & 31, warp = t >> 5;

    {
        u32 sb = (u32)__cvta_generic_to_shared(&B32[t*4]);
        const u32* gs = Wf + t*4;
        #pragma unroll
        for (int i = 0; i < 16; i++)
            cpasync16(sb + i*4096, gs + i*1024);
        asm volatile("cp.async.commit_group;" ::: "memory");
    }

    int bs0 = m0 & ~511;
    int s0  = (m0 & 511) - 3;     // local token of raw row 0
    // stage raw rows (38 x 128) with zero-fill outside the sequence
    #pragma unroll
    for (int i = 0; i < 5; i++) {
        int idx = i*256 + t;          // 1216 float4 slots
        if (idx < 1216) {
            int rr = idx >> 5, c4 = (idx & 31)*4;
            int s = s0 + rr;
            float4 v = {0,0,0,0};
            if ((unsigned)s < 512u)
                v = *(const float4*)&A[(size_t)(bs0 + s)*128 + c4];
            *(float4*)&Raw[rr*128 + c4] = v;
        }
    }
    __syncthreads();

    // per-row LN stats: warp handles rows warp, warp+8, ...
    #pragma unroll
    for (int it = 0; it < 5; it++) {
        int rr = it*8 + warp;
        if (rr < 38) {
            float4 v = *(const float4*)&Raw[rr*128 + lane*4];
            float s = v.x+v.y+v.z+v.w;
            float q = v.x*v.x+v.y*v.y+v.z*v.z+v.w*v.w;
            #pragma unroll
            for (int o = 16; o > 0; o >>= 1) {
                s += __shfl_xor_sync(0xffffffffu, s, o);
                q += __shfl_xor_sync(0xffffffffu, q, o);
            }
            if (lane == 0) {
                float mu = s * (1.0f/128.0f);
                Mu[rr] = mu;
                Ri[rr] = rsqrtf(q * (1.0f/128.0f) - mu*mu + 1e-5f);
            }
        }
    }
    __syncthreads();

    // DW conv producer
    {
        int d = t & 127, q = t >> 7;       // q 0..1, 16 tokens each
        float wr[7];
        #pragma unroll
        for (int kk = 0; kk < 7; kk++) wr[kk] = dww[d*7 + kk];
        float db = dwb[d];
        float gd = lnS[d], bd = lnB[d];
        int kt = d >> 4;
        int tig = (d & 7) >> 1, bb = d & 1;
        int kreg2 = ((d & 15) >> 3) * 2;
        u16* A16 = (u16*)A32;
        float hwin[22];
        #pragma unroll
        for (int jj = 0; jj < 22; jj++) {
            int rr = q*16 + jj;
            int s = s0 + rr;
            float hv = 0.f;
            if ((unsigned)s < 512u)
                hv = (Raw[rr*128 + d] - Mu[rr]) * Ri[rr] * gd + bd;
            hwin[jj] = hv;
        }
        #pragma unroll
        for (int i = 0; i < 16; i++) {
            float acc = db;
            #pragma unroll
            for (int kk = 0; kk < 7; kk++) acc += wr[kk] * hwin[i+kk];
            int ml = q*16 + i;
            int mt = ml >> 4, mm = ml & 15;
            int g = mm & 7, hi8 = mm >> 3;
            int reg = hi8 + kreg2;
            int ln2 = g*4 + tig;
            u16 h = bfhi(acc);
            u16 l = bfhi(acc - bf2f(h));
            int ih = ((mt*8 + kt)*32 + ln2)*4 + reg;
            int il = (((2 + mt)*8 + kt)*32 + ln2)*4 + reg;
            A16[ih*2 + bb] = h;
            A16[il*2 + bb] = l;
        }
    }
    asm volatile("cp.async.wait_group 0;" ::: "memory");
    __syncthreads();

    int wm = warp >> 2, wn = warp & 3;
    int nt0 = wn*4;
    float4 acc[4];
    #pragma unroll
    for (int j = 0; j < 4; j++) acc[j] = make_float4(0.f,0.f,0.f,0.f);

    #pragma unroll
    for (int kt = 0; kt < 8; kt++) {
        uint4 ah = *(const uint4*)&A32[((wm*8 + kt)*32 + lane)*4];
        uint4 al = *(const uint4*)&A32[(((2+wm)*8 + kt)*32 + lane)*4];
        uint2 bh[4], bl[4];
        #pragma unroll
        for (int j = 0; j < 4; j++) {
            bh[j] = *(const uint2*)&B32[((kt*16 + nt0+j)*32 + lane)*2];
            bl[j] = *(const uint2*)&B32[(((8+kt)*16 + nt0+j)*32 + lane)*2];
        }
        #pragma unroll
        for (int j = 0; j < 4; j++) {
            mma16816(acc[j], ah, bh[j]);
            mma16816(acc[j], ah, bl[j]);
            mma16816(acc[j], al, bh[j]);
        }
    }
    __syncthreads();

    #pragma unroll
    for (int j = 0; j < 4; j++) {
        int row = wm*16 + (lane >> 2);
        int col = (nt0+j)*8 + (lane & 3)*2;
        float2 lo = {acc[j].x, acc[j].y};
        float2 hi = {acc[j].z, acc[j].w};
        *(float2*)&Csm[row*132 + col]     = lo;
        *(float2*)&Csm[(row+8)*132 + col] = hi;
    }
    __syncthreads();

    int colE = lane*4;
    float4 bv = *(const float4*)&bias[colE];
    #pragma unroll
    for (int i = 0; i < 4; i++) {
        int row = warp*4 + i;
        int m = m0 + row;
        float4 c4 = *(const float4*)&Csm[row*132 + colE];
        float4 r4 = *(const float4*)&Raw[(row+3)*128 + colE];   // residual = original out rows
        float v0 = fmaxf(c4.x + bv.x, 0.f) + r4.x;
        float v1 = fmaxf(c4.y + bv.y, 0.f) + r4.y;
        float v2 = fmaxf(c4.z + bv.z, 0.f) + r4.z;
        float v3 = fmaxf(c4.w + bv.w, 0.f) + r4.w;
        float4 ov = {v0, v1, v2, v3};
        *(float4*)&out[(size_t)m*128 + colE] = ov;
    }
}

// ============ gemmFF: fused LN -> F1 -> ReLU -> F2 -> +res ============
// M=64 tile, 512 thr. smem: B1 @0 (16384), B2 @16384 (16384), A @32768 (8448, union Csm)
__global__ __launch_bounds__(512) void gemmFF(
    const float* __restrict__ A, const u32* __restrict__ W1, const u32* __restrict__ W2,
    const float* __restrict__ b1, const float* __restrict__ b2,
    float* __restrict__ out,
    const float* __restrict__ lnS, const float* __restrict__ lnB)
{
    extern __shared__ u32 smu[];
    u32* B1 = smu;
    u32* B2 = smu + 16384;
    u32* A32 = smu + 32768;
    float* Csm = (float*)(smu + 32768);

    int m0 = blockIdx.x * 64;
    int t = threadIdx.x, lane = t & 31, warp = t >> 5;

    {
        u32 sb1 = (u32)__cvta_generic_to_shared(&B1[t*4]);
        const u32* g1 = W1 + t*4;
        #pragma unroll
        for (int i = 0; i < 8; i++)
            cpasync16(sb1 + i*8192, g1 + i*2048);
        asm volatile("cp.async.commit_group;" ::: "memory");
        u32 sb2 = (u32)__cvta_generic_to_shared(&B2[t*4]);
        const u32* g2 = W2 + t*4;
        #pragma unroll
        for (int i = 0; i < 8; i++)
            cpasync16(sb2 + i*8192, g2 + i*2048);
        asm volatile("cp.async.commit_group;" ::: "memory");
    }

    // LN producer: warp (0..15) owns rows 4w..4w+3
    {
        int k0 = lane*4;
        float4 g4 = *(const float4*)&lnS[k0];
        float4 b4 = *(const float4*)&lnB[k0];
        int kt = k0 >> 4;
        #pragma unroll
        for (int rr = 0; rr < 4; rr++) {
            int ml = warp*4 + rr;
            float4 v = *(const float4*)&A[(size_t)(m0 + ml)*128 + k0];
            float vv[4] = {v.x, v.y, v.z, v.w};
            float s = vv[0]+vv[1]+vv[2]+vv[3];
            float q = vv[0]*vv[0]+vv[1]*vv[1]+vv[2]*vv[2]+vv[3]*vv[3];
            #pragma unroll
            for (int o = 16; o > 0; o >>= 1) {
                s += __shfl_xor_sync(0xffffffffu, s, o);
                q += __shfl_xor_sync(0xffffffffu, q, o);
            }
            float mu = s * (1.0f/128.0f);
            float var = q * (1.0f/128.0f) - mu*mu;
            float ri = rsqrtf(var + 1e-5f);
            vv[0] = (vv[0]-mu)*ri*g4.x + b4.x;
            vv[1] = (vv[1]-mu)*ri*g4.y + b4.y;
            vv[2] = (vv[2]-mu)*ri*g4.z + b4.z;
            vv[3] = (vv[3]-mu)*ri*g4.w + b4.w;
            int mt = ml >> 4, mm = ml & 15;
            int g = mm & 7, hi8 = mm >> 3;
            #pragma unroll
            for (int j = 0; j < 4; j += 2) {
                int k = k0 + j;
                int tig = (k & 7) >> 1;
                int reg = hi8 + 2*((k & 15) >> 3);
                int ln2 = g*4 + tig;
                u32 hi, lo;
                split2(vv[j], vv[j+1], hi, lo);
                A32[((mt*8 + kt)*32 + ln2)*4 + reg]     = hi;
                A32[(((4+mt)*8 + kt)*32 + ln2)*4 + reg] = lo;
            }
        }
    }
    asm volatile("cp.async.wait_group 1;" ::: "memory");
    __syncthreads();

    int wm = warp >> 2, wn = warp & 3;
    int nt0 = wn*4;
    float4 acc[4];
    #pragma unroll
    for (int j = 0; j < 4; j++) acc[j] = make_float4(0.f,0.f,0.f,0.f);

    #pragma unroll
    for (int kt = 0; kt < 8; kt++) {
        uint4 ah = *(const uint4*)&A32[((wm*8 + kt)*32 + lane)*4];
        uint4 al = *(const uint4*)&A32[(((4+wm)*8 + kt)*32 + lane)*4];
        uint2 bh[4], bl[4];
        #pragma unroll
        for (int j = 0; j < 4; j++) {
            bh[j] = *(const uint2*)&B1[((kt*16 + nt0+j)*32 + lane)*2];
            bl[j] = *(const uint2*)&B1[(((8+kt)*16 + nt0+j)*32 + lane)*2];
        }
        #pragma unroll
        for (int j = 0; j < 4; j++) {
            mma16816(acc[j], ah, bh[j]);
            mma16816(acc[j], ah, bl[j]);
            mma16816(acc[j], al, bh[j]);
        }
    }
    __syncthreads();   // all warps done reading A1

    // bias1 + relu + split -> A2 frags (C-frag == A-frag identity)
    {
        int cb = (lane & 3)*2;
        #pragma unroll
        for (int j = 0; j < 4; j++) {
            int nt = nt0 + j;
            float2 bb = *(const float2*)&b1[nt*8 + cb];
            float r0 = fmaxf(acc[j].x + bb.x, 0.f);
            float r1 = fmaxf(acc[j].y + bb.y, 0.f);
            float r2 = fmaxf(acc[j].z + bb.x, 0.f);
            float r3 = fmaxf(acc[j].w + bb.y, 0.f);
            u32 hiX, loX, hiY, loY;
            split2(r0, r1, hiX, loX);
            split2(r2, r3, hiY, loY);
            int kt = nt >> 1, half = nt & 1;
            int baseH = ((wm*8 + kt)*32 + lane)*4;
            int baseL = (((4+wm)*8 + kt)*32 + lane)*4;
            A32[baseH + (half ? 2 : 0)] = hiX;
            A32[baseH + (half ? 3 : 1)] = hiY;
            A32[baseL + (half ? 2 : 0)] = loX;
            A32[baseL + (half ? 3 : 1)] = loY;
        }
    }
    asm volatile("cp.async.wait_group 0;" ::: "memory");
    __syncthreads();

    float4 acc2[4];
    #pragma unroll
    for (int j = 0; j < 4; j++) acc2[j] = make_float4(0.f,0.f,0.f,0.f);

    #pragma unroll
    for (int kt = 0; kt < 8; kt++) {
        uint4 ah = *(const uint4*)&A32[((wm*8 + kt)*32 + lane)*4];
        uint4 al = *(const uint4*)&A32[(((4+wm)*8 + kt)*32 + lane)*4];
        uint2 bh[4], bl[4];
        #pragma unroll
        for (int j = 0; j < 4; j++) {
            bh[j] = *(const uint2*)&B2[((kt*16 + nt0+j)*32 + lane)*2];
            bl[j] = *(const uint2*)&B2[(((8+kt)*16 + nt0+j)*32 + lane)*2];
        }
        #pragma unroll
        for (int j = 0; j < 4; j++) {
            mma16816(acc2[j], ah, bh[j]);
            mma16816(acc2[j], ah, bl[j]);
            mma16816(acc2[j], al, bh[j]);
        }
    }
    __syncthreads();

    #pragma unroll
    for (int j = 0; j < 4; j++) {
        int row = wm*16 + (lane >> 2);
        int col = (nt0+j)*8 + (lane & 3)*2;
        float2 lo = {acc2[j].x, acc2[j].y};
        float2 hi = {acc2[j].z, acc2[j].w};
        *(float2*)&Csm[row*132 + col]     = lo;
        *(float2*)&Csm[(row+8)*132 + col] = hi;
    }
    __syncthreads();

    int colE = lane*4;
    float4 bv = *(const float4*)&b2[colE];
    #pragma unroll
    for (int i = 0; i < 4; i++) {
        int row = warp*4 + i;                   // 0..63
        int m = m0 + row;
        float4 c4 = *(const float4*)&Csm[row*132 + colE];
        float4 r4 = *(const float4*)&out[(size_t)m*128 + colE];
        float4 ov;
        ov.x = c4.x + bv.x + r4.x;
        ov.y = c4.y + bv.y + r4.y;
        ov.z = c4.z + bv.z + r4.z;
        ov.w = c4.w + bv.w + r4.w;
        *(float4*)&out[(size_t)m*128 + colE] = ov;
    }
}

// ---------------- repack K,V into mma.sync B-fragments ----------------
__global__ __launch_bounds__(256) void kvRepack(const float* __restrict__ qkv,
                                                u32* __restrict__ kvF) {
    __shared__ u32 st[8192];
    int mat = blockIdx.x;
    int bh = blockIdx.y;
    int b = bh >> 3, h = bh & 7;
    const float* src = qkv + (size_t)(1 + mat)*ELEMS;
    int t = threadIdx.x;
    int key0 = t*2;

    float v0[16], v1[16];
    const float* p0 = src + (size_t)(b*512 + key0)*128 + h*16;
    const float* p1 = p0 + 128;
    #pragma unroll
    for (int i = 0; i < 4; i++) {
        *(float4*)&v0[i*4] = *(const float4*)(p0 + i*4);
        *(float4*)&v1[i*4] = *(const float4*)(p1 + i*4);
    }

    if (mat == 0) {
        #pragma unroll
        for (int w = 0; w < 2; w++) {
            const float* vv = (w == 0) ? v0 : v1;
            int key = key0 + w;
            int nt = key >> 3;
            int laneb = (key & 7)*4;
            #pragma unroll
            for (int dp = 0; dp < 8; dp++) {
                int tig = dp & 3, reg = dp >> 2;
                u32 hi, lo;
                split2(vv[2*dp], vv[2*dp+1], hi, lo);
                int idx = ((nt*32) + laneb + tig)*2 + reg;
                st[idx] = hi; st[4096 + idx] = lo;
            }
        }
    } else {
        int kt = key0 >> 4;
        int tig = (key0 >> 1) & 3;
        int reg = (key0 & 15) >> 3;
        #pragma unroll
        for (int d = 0; d < 16; d++) {
            u32 hi, lo;
            split2(v0[d], v1[d], hi, lo);
            int nt = d >> 3, nn = d & 7;
            int idx = ((kt*2 + nt)*32 + nn*4 + tig)*2 + reg;
            st[idx] = hi; st[4096 + idx] = lo;
        }
    }
    __syncthreads();
    u32* dst = kvF + (size_t)(mat*128 + bh)*8192;
    #pragma unroll
    for (int i = 0; i < 8; i++)
        *(uint4*)&dst[i*1024 + t*4] = *(const uint4*)&st[i*1024 + t*4];
}

// ---------------- mma.sync flash attention ----------------
__global__ __launch_bounds__(128) void attnT(const float* __restrict__ qkv,
                                             const u32* __restrict__ kvF,
                                             const int* __restrict__ mask,
                                             float* __restrict__ out) {
    __shared__ float Ms[512];
    int bh = blockIdx.y;
    int b = bh >> 3, h = bh & 7;
    int qbase = blockIdx.x * 128;
    int t = threadIdx.x, lane = t & 31, warp = t >> 5;
    int c2 = (lane & 3)*2;

    #pragma unroll
    for (int i = 0; i < 4; i++) {
        int key = i*128 + t;
        Ms[key] = mask[b*512 + key] ? 0.f : -1e30f;
    }
    __syncthreads();

    const u32* Kf = kvF + (size_t)bh * 8192;
    const u32* Vf = kvF + (size_t)(128 + bh) * 8192;

    const float qsc = 0.25f * 1.4426950408889634f;
    uint4 qh[2], ql[2];
    #pragma unroll
    for (int i = 0; i < 2; i++) {
        int r = qbase + warp*32 + i*16 + (lane >> 2);
        const float* b0p = qkv + (size_t)(b*512 + r)*128 + h*16;
        const float* b1p = b0p + 8*128;
        float2 fa = *(const float2*)(b0p + c2);
        float2 fc = *(const float2*)(b0p + c2 + 8);
        float2 fb = *(const float2*)(b1p + c2);
        float2 fd = *(const float2*)(b1p + c2 + 8);
        fa.x *= qsc; fa.y *= qsc; fb.x *= qsc; fb.y *= qsc;
        fc.x *= qsc; fc.y *= qsc; fd.x *= qsc; fd.y *= qsc;
        split2(fa.x, fa.y, qh[i].x, ql[i].x);
        split2(fb.x, fb.y, qh[i].y, ql[i].y);
        split2(fc.x, fc.y, qh[i].z, ql[i].z);
        split2(fd.x, fd.y, qh[i].w, ql[i].w);
    }

    float4 oAcc[2][2];
    float lAcc[2][2];
    #pragma unroll
    for (int i = 0; i < 2; i++) {
        oAcc[i][0] = make_float4(0,0,0,0);
        oAcc[i][1] = make_float4(0,0,0,0);
        lAcc[i][0] = 0.f; lAcc[i][1] = 0.f;
    }

    for (int kb = 0; kb < 8; kb++) {
        #pragma unroll
        for (int ktl = 0; ktl < 4; ktl++) {
            int nt0 = kb*8 + ktl*2;
            uint2 kh0 = *(const uint2*)&Kf[(nt0*32 + lane)*2];
            uint2 kh1 = *(const uint2*)&Kf[((nt0+1)*32 + lane)*2];
            uint2 kl0 = *(const uint2*)&Kf[4096 + (nt0*32 + lane)*2];
            uint2 kl1 = *(const uint2*)&Kf[4096 + ((nt0+1)*32 + lane)*2];

            float4 s[2][2];
            #pragma unroll
            for (int i = 0; i < 2; i++) {
                s[i][0] = make_float4(0,0,0,0);
                s[i][1] = make_float4(0,0,0,0);
                mma16816(s[i][0], qh[i], kh0);
                mma16816(s[i][0], ql[i], kh0);
                mma16816(s[i][0], qh[i], kl0);
                mma16816(s[i][1], qh[i], kh1);
                mma16816(s[i][1], ql[i], kh1);
                mma16816(s[i][1], qh[i], kl1);
            }

            int colb = nt0*8 + c2;
            float m00 = Ms[colb],     m01 = Ms[colb+1];
            float m10 = Ms[colb+8],   m11 = Ms[colb+9];

            uint4 pah[2], pal[2];
            #pragma unroll
            for (int i = 0; i < 2; i++) {
                float px0 = ex2f(s[i][0].x + m00);
                float py0 = ex2f(s[i][0].y + m01);
                float pz0 = ex2f(s[i][0].z + m00);
                float pw0 = ex2f(s[i][0].w + m01);
                float px1 = ex2f(s[i][1].x + m10);
                float py1 = ex2f(s[i][1].y + m11);
                float pz1 = ex2f(s[i][1].z + m10);
                float pw1 = ex2f(s[i][1].w + m11);
                lAcc[i][0] += px0 + py0 + px1 + py1;
                lAcc[i][1] += pz0 + pw0 + pz1 + pw1;
                split2(px0, py0, pah[i].x, pal[i].x);
                split2(pz0, pw0, pah[i].y, pal[i].y);
                split2(px1, py1, pah[i].z, pal[i].z);
                split2(pz1, pw1, pah[i].w, pal[i].w);
            }

            int ktg = kb*4 + ktl;
            uint2 vh0 = *(const uint2*)&Vf[((ktg*2 + 0)*32 + lane)*2];
            uint2 vh1 = *(const uint2*)&Vf[((ktg*2 + 1)*32 + lane)*2];
            uint2 vl0 = *(const uint2*)&Vf[4096 + ((ktg*2 + 0)*32 + lane)*2];
            uint2 vl1 = *(const uint2*)&Vf[4096 + ((ktg*2 + 1)*32 + lane)*2];
            #pragma unroll
            for (int i = 0; i < 2; i++) {
                mma16816(oAcc[i][0], pah[i], vh0);
                mma16816(oAcc[i][0], pal[i], vh0);
                mma16816(oAcc[i][0], pah[i], vl0);
                mma16816(oAcc[i][1], pah[i], vh1);
                mma16816(oAcc[i][1], pal[i], vh1);
                mma16816(oAcc[i][1], pah[i], vl1);
            }
        }
    }

    #pragma unroll
    for (int i = 0; i < 2; i++)
        #pragma unroll
        for (int j = 0; j < 2; j++) {
            lAcc[i][j] += __shfl_xor_sync(0xffffffffu, lAcc[i][j], 1);
            lAcc[i][j] += __shfl_xor_sync(0xffffffffu, lAcc[i][j], 2);
        }

    #pragma unroll
    for (int i = 0; i < 2; i++) {
        float inv0 = 1.f / lAcc[i][0];
        float inv1 = 1.f / lAcc[i][1];
        int r = qbase + warp*32 + i*16 + (lane >> 2);
        #pragma unroll
        for (int n = 0; n < 2; n++) {
            float* op = out + (size_t)(b*512 + r)*128 + h*16 + n*8 + c2;
            float2 lo = {oAcc[i][n].x * inv0, oAcc[i][n].y * inv0};
            float2 hi = {oAcc[i][n].z * inv1, oAcc[i][n].w * inv1};
            *(float2*)op = lo;
            *(float2*)(op + 8*128) = hi;
        }
    }
}

// ---------------- launch ----------------
extern "C" void kernel_launch(void* const* d_in, const int* in_sizes, int n_in,
                              void* d_out, int out_size) {
    const float* x     = (const float*)d_in[0];
    const int*   mask  = (const int*)  d_in[1];
    const float* ln_s  = (const float*)d_in[2];
    const float* ln_b  = (const float*)d_in[3];
    const float* dw_w  = (const float*)d_in[4];
    const float* dw_b  = (const float*)d_in[5];
    const float* pw_w  = (const float*)d_in[6];
    const float* pw_b  = (const float*)d_in[7];
    const float* Wq    = (const float*)d_in[8];
    const float* Wk    = (const float*)d_in[9];
    const float* Wv    = (const float*)d_in[10];
    const float* Wo    = (const float*)d_in[11];
    const float* ab    = (const float*)d_in[12];
    const float* f1w   = (const float*)d_in[13];
    const float* f1b   = (const float*)d_in[14];
    const float* f2w   = (const float*)d_in[15];
    const float* f2b   = (const float*)d_in[16];
    float* out = (float*)d_out;

    float *hP, *aP, *qkvP;
    u32 *wBP, *kvFP;
    cudaGetSymbolAddress((void**)&hP,   g_h);
    cudaGetSymbolAddress((void**)&aP,   g_a);
    cudaGetSymbolAddress((void**)&qkvP, g_qkv);
    cudaGetSymbolAddress((void**)&wBP,  g_wB);
    cudaGetSymbolAddress((void**)&kvFP, g_kvF);

    const int NSM = (16384 + 4224) * 4;            // 82432
    const int CSM = 25600 * 4;                     // 102400
    const int FSM = (16384*2 + 8448) * 4;          // 164864

    auto gQKV = gemmNT<true,  true,  2, false>;
    auto gWo  = gemmNT<false, false, 2, true>;
    cudaFuncSetAttribute(gQKV,      cudaFuncAttributeMaxDynamicSharedMemorySize, NSM);
    cudaFuncSetAttribute(gWo,       cudaFuncAttributeMaxDynamicSharedMemorySize, NSM);
    cudaFuncSetAttribute(gemmConvF, cudaFuncAttributeMaxDynamicSharedMemorySize, CSM);
    cudaFuncSetAttribute(gemmFF,    cudaFuncAttributeMaxDynamicSharedMemorySize, FSM);

    prep_weights<<<640, 256>>>(Wq, Wk, Wv, pw_w, f1w, f2w, Wo, wBP);
    addpos<<<128, 512>>>(x, out);

    // conv stack: ping-pong out <-> hP (halo forbids in-place)
    float* O[2] = {out, hP};
    for (int i = 0; i < 4; i++) {
        gemmConvF<<<256, 256, CSM>>>(O[i&1], wBP + (size_t)(3+i)*16384, pw_b + i*128,
                                     O[(i&1)^1],
                                     ln_s + i*128, ln_b + i*128,
                                     dw_w + i*896, dw_b + i*128);
    }
    // after 4 layers, residual stream is back in `out`

    gQKV<<<dim3(256,3), 256, NSM>>>(out, wBP, ab, nullptr, qkvP,
                                    ln_s + 4*128, ln_b + 4*128);
    kvRepack<<<dim3(2,128), 256>>>(qkvP, kvFP);
    attnT<<<dim3(4,128), 128>>>(qkvP, kvFP, mask, aP);
    gWo<<<256, 256, NSM>>>(aP, wBP + (size_t)9*16384, ab, out, out,
                           nullptr, nullptr);
    gemmFF<<<128, 512, FSM>>>(out, wBP + (size_t)7*16384, wBP + (size_t)8*16384,
                              f1b, f2b, out, ln_s + 5*128, ln_b + 5*128);
}

// round 15
// speedup vs baseline: 1.6899x; 1.6899x over previous
#include <cuda_runtime.h>
#include <cuda_bf16.h>
#include <math.h>

#define TOKS 8192
#define ELEMS 1048576
typedef unsigned long long ull;
typedef unsigned int u32;
typedef unsigned short u16;

// ---------------- scratch ----------------
__device__ float g_h[ELEMS];
__device__ float g_h2[ELEMS];
__device__ float g_a[ELEMS];
__device__ float g_qkv[3*ELEMS];
__device__ u32 g_wB[10*16384];      // weights in B-frag order, hi/lo split
__device__ u32 g_kvF[2*128*8192];   // K,V frags per (b,h)

// ---------------- helpers ----------------
__device__ __forceinline__ u16 bfhi(float v) {
    return __bfloat16_as_ushort(__float2bfloat16_rn(v));
}
__device__ __forceinline__ float bf2f(u16 u) {
    return __bfloat162float(__ushort_as_bfloat16(u));
}
__device__ __forceinline__ float ex2f(float x) {
    float r; asm("ex2.approx.f32 %0, %1;" : "=f"(r) : "f"(x)); return r;
}
__device__ __forceinline__ u32 cvtbf2(float hi, float lo) {
    u32 r; asm("cvt.rn.bf16x2.f32 %0, %1, %2;" : "=r"(r) : "f"(hi), "f"(lo)); return r;
}
__device__ __forceinline__ void mma16816(float4& c, const uint4& a, const uint2& b) {
    asm("mma.sync.aligned.m16n8k16.row.col.f32.bf16.bf16.f32 "
        "{%0,%1,%2,%3}, {%4,%5,%6,%7}, {%8,%9}, {%0,%1,%2,%3};"
        : "+f"(c.x), "+f"(c.y), "+f"(c.z), "+f"(c.w)
        : "r"(a.x), "r"(a.y), "r"(a.z), "r"(a.w), "r"(b.x), "r"(b.y));
}
__device__ __forceinline__ void split2(float f0, float f1, u32& hi, u32& lo) {
    hi = cvtbf2(f1, f0);
    float h0 = __uint_as_float(hi << 16);
    float h1 = __uint_as_float(hi & 0xFFFF0000u);
    lo = cvtbf2(f1 - h1, f0 - h0);
}
__device__ __forceinline__ void cpasync16(u32 saddr, const void* g) {
    asm volatile("cp.async.cg.shared.global [%0], [%1], 16;" :: "r"(saddr), "l"(g));
}

// ---------------- weight prep ----------------
__global__ void prep_weights(const float* __restrict__ Wq, const float* __restrict__ Wk,
                             const float* __restrict__ Wv, const float* __restrict__ pw,
                             const float* __restrict__ f1, const float* __restrict__ f2,
                             const float* __restrict__ Wo, u32* __restrict__ wB) {
    int idx = blockIdx.x*256 + threadIdx.x;          // 10*16384
    if (idx >= 10*16384) return;
    int j = idx >> 14, r = idx & 16383;
    int k = r >> 7, n = r & 127;
    float v;
    if (j < 3) {
        const float* W = (j==0) ? Wq : (j==1) ? Wk : Wv;   // (H,128,16)
        v = W[(n>>4)*2048 + k*16 + (n&15)];
    } else if (j < 7) {
        v = pw[(j-3)*16384 + n*128 + k];
    } else if (j < 9) {
        const float* W = (j==7) ? f1 : f2;
        v = W[n*128 + k];
    } else {
        v = Wo[k*128 + n];
    }
    u16 h = bfhi(v);
    u16 l = bfhi(v - bf2f(h));
    int kt = k >> 4, kk = k & 15;
    int reg = kk >> 3, tig = (kk & 7) >> 1, bb = kk & 1;
    int nt = n >> 3, lane = (n & 7)*4 + tig;
    u16* w16 = (u16*)(wB + (size_t)j*16384);
    int i32h = ((kt*16 + nt)*32 + lane)*2 + reg;
    int i32l = (((8 + kt)*16 + nt)*32 + lane)*2 + reg;
    w16[i32h*2 + bb] = h;
    w16[i32l*2 + bb] = l;
}

// ---------------- addpos + LN0 ----------------
__global__ __launch_bounds__(512) void addpos_ln(const float* __restrict__ x,
                                                 float* __restrict__ out, float* __restrict__ hout,
                                                 const float* __restrict__ lnS,
                                                 const float* __restrict__ lnB) {
    int m0 = blockIdx.x * 64;
    int lane = threadIdx.x & 31, warp = threadIdx.x >> 5;
    int col = lane * 4;
    const float inc = 0.14619588050756158f;   // log(10000)/63
    float4 g4 = *(const float4*)&lnS[col];
    float4 b4 = *(const float4*)&lnB[col];
    #pragma unroll
    for (int i = 0; i < 4; i++) {
        int m = m0 + warp*4 + i;
        int s = m & 511;
        float4 xv = *(const float4*)&x[m*128 + col];
        float v[4] = {xv.x, xv.y, xv.z, xv.w};
        #pragma unroll
        for (int jj = 0; jj < 4; jj++) {
            int d = col + jj;
            int dd = d & 63;
            float a = (float)s * expf(-inc*(float)dd);
            v[jj] += (d < 64) ? sinf(a) : cosf(a);
        }
        float rs_ = v[0]+v[1]+v[2]+v[3];
        float rq  = v[0]*v[0]+v[1]*v[1]+v[2]*v[2]+v[3]*v[3];
        #pragma unroll
        for (int o = 16; o > 0; o >>= 1) {
            rs_ += __shfl_xor_sync(0xffffffffu, rs_, o);
            rq  += __shfl_xor_sync(0xffffffffu, rq,  o);
        }
        float mu  = rs_ * (1.0f/128.0f);
        float var = rq  * (1.0f/128.0f) - mu*mu;
        float rinv = rsqrtf(var + 1e-5f);
        float4 ov = {v[0], v[1], v[2], v[3]};
        *(float4*)&out[m*128 + col] = ov;
        float4 hv;
        hv.x = (v[0]-mu)*rinv*g4.x + b4.x;
        hv.y = (v[1]-mu)*rinv*g4.y + b4.y;
        hv.z = (v[2]-mu)*rinv*g4.z + b4.z;
        hv.w = (v[3]-mu)*rinv*g4.w + b4.w;
        *(float4*)&hout[m*128 + col] = hv;
    }
}

// ---------------- tensor-core GEMM: 32xM tile, K=128, N=128, 256 thr ----------------
// B staged into smem via cp.async, overlapped with the A producer.
// KVF: blockIdx.y==1/2 emit K/V mma-fragments directly (skip plain rows).
template<bool DW, bool MULTI, int BIASM, bool RELU, bool RES, bool LN, bool KVF>
__global__ __launch_bounds__(256) void gemmT(
    const float* __restrict__ A, const u32* __restrict__ Wf,
    const float* __restrict__ bias, const float* __restrict__ res,
    float* __restrict__ out, float* __restrict__ hout,
    const float* __restrict__ lnS, const float* __restrict__ lnB,
    const float* __restrict__ dww, const float* __restrict__ dwb,
    u32* __restrict__ kvF)
{
    extern __shared__ u32 smu[];
    u32* B32 = smu;                       // 16384 u32 (64 KB)
    u32* A32 = smu + 16384;               // 4096 u32
    float* Csm = (float*)(smu + 16384);   // 32 x 132 f32 (aliased with A32 region)
    if (MULTI) { Wf += blockIdx.y * 16384; out += (size_t)blockIdx.y * ELEMS; }

    int m0 = blockIdx.x * 32;
    int t = threadIdx.x, lane = t & 31, warp = t >> 5;

    // kick off B staging: 16 x 16B per thread, async into smem
    {
        u32 sbase = (u32)__cvta_generic_to_shared(&B32[t*4]);
        const u32* gsrc = Wf + t*4;
        #pragma unroll
        for (int i = 0; i < 16; i++)
            cpasync16(sbase + i*4096, gsrc + i*1024);
        asm volatile("cp.async.commit_group;" ::: "memory");
    }

    // A producer overlaps with B copies
    u16* A16 = (u16*)A32;
    if (DW) {
        int d = t & 127, q = t >> 7;       // q in {0,1}, 16 tokens each
        float wr[7];
        #pragma unroll
        for (int kk = 0; kk < 7; kk++) wr[kk] = dww[d*7 + kk];
        float db = dwb[d];
        int kt = d >> 4;
        int tig = (d & 7) >> 1, bb = d & 1;
        int kreg2 = ((d & 15) >> 3) * 2;
        const float* hb = A + (size_t)(m0 & ~511) * 128;
        int sBase = (m0 & 511) + q*16;
        float hwin[22];
        #pragma unroll
        for (int jj = 0; jj < 22; jj++) {
            int s = sBase + jj - 3;
            hwin[jj] = (s >= 0 && s < 512) ? hb[s*128 + d] : 0.f;
        }
        #pragma unroll
        for (int i = 0; i < 16; i++) {
            float acc = db;
            #pragma unroll
            for (int kk = 0; kk < 7; kk++) acc += wr[kk] * hwin[i+kk];
            int ml = q*16 + i;
            int mt = ml >> 4, mm = ml & 15;
            int g = mm & 7, hi8 = mm >> 3;
            int reg = hi8 + kreg2;
            int ln2 = g*4 + tig;
            u16 h = bfhi(acc);
            u16 l = bfhi(acc - bf2f(h));
            int ih = ((mt*8 + kt)*32 + ln2)*4 + reg;
            int il = (((2 + mt)*8 + kt)*32 + ln2)*4 + reg;
            A16[ih*2 + bb] = h;
            A16[il*2 + bb] = l;
        }
    } else {
        #pragma unroll
        for (int i = 0; i < 4; i++) {
            int idx4 = i*256 + t;
            int m = idx4 >> 5;                  // 0..31
            int k0 = (idx4 & 31) * 4;
            float4 v = *(const float4*)&A[(size_t)(m0 + m)*128 + k0];
            float vv[4] = {v.x, v.y, v.z, v.w};
            int mt = m >> 4, mm = m & 15;
            int g = mm & 7, hi8 = mm >> 3;
            int kt = k0 >> 4;
            #pragma unroll
            for (int j = 0; j < 4; j += 2) {
                int k = k0 + j;
                int tig = (k & 7) >> 1;
                int reg = hi8 + 2*((k & 15) >> 3);
                int ln2 = g*4 + tig;
                u32 hi, lo;
                split2(vv[j], vv[j+1], hi, lo);
                A32[((mt*8 + kt)*32 + ln2)*4 + reg]     = hi;
                A32[(((2+mt)*8 + kt)*32 + ln2)*4 + reg] = lo;
            }
        }
    }
    asm volatile("cp.async.wait_group 0;" ::: "memory");
    __syncthreads();

    // mainloop: warp = (wm in 0..1, wn in 0..3)
    int wm = warp >> 2, wn = warp & 3;
    int nt0 = wn*4;
    float4 acc[4];
    #pragma unroll
    for (int j = 0; j < 4; j++) acc[j] = make_float4(0.f,0.f,0.f,0.f);

    #pragma unroll
    for (int kt = 0; kt < 8; kt++) {
        uint4 ah = *(const uint4*)&A32[((wm*8 + kt)*32 + lane)*4];
        uint4 al = *(const uint4*)&A32[(((2+wm)*8 + kt)*32 + lane)*4];
        uint2 bh[4], bl[4];
        #pragma unroll
        for (int j = 0; j < 4; j++) {
            bh[j] = *(const uint2*)&B32[((kt*16 + nt0+j)*32 + lane)*2];
            bl[j] = *(const uint2*)&B32[(((8+kt)*16 + nt0+j)*32 + lane)*2];
        }
        #pragma unroll
        for (int j = 0; j < 4; j++) {
            mma16816(acc[j], ah, bh[j]);
            mma16816(acc[j], ah, bl[j]);
            mma16816(acc[j], al, bh[j]);
        }
    }
    __syncthreads();

    #pragma unroll
    for (int j = 0; j < 4; j++) {
        int row = wm*16 + (lane >> 2);
        int col = (nt0+j)*8 + (lane & 3)*2;
        float2 lo = {acc[j].x, acc[j].y};
        float2 hi = {acc[j].z, acc[j].w};
        *(float2*)&Csm[row*132 + col]     = lo;
        *(float2*)&Csm[(row+8)*132 + col] = hi;
    }
    __syncthreads();

    int colE = lane*4;
    float4 bv = {0,0,0,0};
    if (BIASM == 1) bv = *(const float4*)&bias[colE];
    float bs = (BIASM == 2) ? bias[0] : 0.f;
    float4 g4 = {0,0,0,0}, lb4 = {0,0,0,0};
    if (LN) { g4 = *(const float4*)&lnS[colE]; lb4 = *(const float4*)&lnB[colE]; }

    // compute all 4 rows' values first
    float va[4][4];
    #pragma unroll
    for (int i = 0; i < 4; i++) {
        int row = warp*4 + i;
        int m = m0 + row;
        float4 c4 = *(const float4*)&Csm[row*132 + colE];
        float v[4] = {c4.x, c4.y, c4.z, c4.w};
        #pragma unroll
        for (int jj = 0; jj < 4; jj++) {
            float val = v[jj];
            if (BIASM == 1) val += ((const float*)&bv)[jj];
            if (BIASM == 2) val += bs;
            if (RELU) val = fmaxf(val, 0.f);
            v[jj] = val;
        }
        if (RES) {
            float4 r4 = *(const float4*)&res[(size_t)m*128 + colE];
            v[0] += r4.x; v[1] += r4.y; v[2] += r4.z; v[3] += r4.w;
        }
        va[i][0] = v[0]; va[i][1] = v[1]; va[i][2] = v[2]; va[i][3] = v[3];
    }

    if (KVF && blockIdx.y != 0) {
        // emit mma B-fragments for K (y==1) or V (y==2), mirroring kvRepack
        int mat = blockIdx.y - 1;
        int b = m0 >> 9;
        int h = colE >> 4;
        u32* dst = kvF + ((size_t)(mat*128) + b*8 + h) * 8192;
        int ld0 = colE & 15;                       // local dim 0..15 within head
        if (mat == 0) {
            // K: pairs along dims, per key (row)
            #pragma unroll
            for (int i = 0; i < 4; i++) {
                int key = (m0 & 511) + warp*4 + i;
                int nt = key >> 3, laneb = (key & 7)*4;
                int dp0 = ld0 >> 1;                // in {0,2,4,6}
                u32 hi, lo;
                split2(va[i][0], va[i][1], hi, lo);
                int idx = (nt*32 + laneb + (dp0 & 3))*2 + (dp0 >> 2);
                dst[idx] = hi; dst[4096 + idx] = lo;
                int dp1 = dp0 + 1;
                split2(va[i][2], va[i][3], hi, lo);
                idx = (nt*32 + laneb + (dp1 & 3))*2 + (dp1 >> 2);
                dst[idx] = hi; dst[4096 + idx] = lo;
            }
        } else {
            // V: pairs along adjacent keys (rows), per dim
            #pragma unroll
            for (int p = 0; p < 2; p++) {
                int key0 = (m0 & 511) + warp*4 + p*2;
                int kt = key0 >> 4, tig = (key0 >> 1) & 3, reg = (key0 & 15) >> 3;
                #pragma unroll
                for (int e = 0; e < 4; e++) {
                    int ld = ld0 + e;
                    int nt = ld >> 3, nn = ld & 7;
                    u32 hi, lo;
                    split2(va[p*2][e], va[p*2+1][e], hi, lo);
                    int idx = ((kt*2 + nt)*32 + nn*4 + tig)*2 + reg;
                    dst[idx] = hi; dst[4096 + idx] = lo;
                }
            }
        }
    } else {
        #pragma unroll
        for (int i = 0; i < 4; i++) {
            int m = m0 + warp*4 + i;
            float4 ov = {va[i][0], va[i][1], va[i][2], va[i][3]};
            *(float4*)&out[(size_t)m*128 + colE] = ov;
            if (LN) {
                float v0 = va[i][0], v1 = va[i][1], v2 = va[i][2], v3 = va[i][3];
                float rs_ = v0+v1+v2+v3;
                float rq  = v0*v0+v1*v1+v2*v2+v3*v3;
                #pragma unroll
                for (int o = 16; o > 0; o >>= 1) {
                    rs_ += __shfl_xor_sync(0xffffffffu, rs_, o);
                    rq  += __shfl_xor_sync(0xffffffffu, rq,  o);
                }
                float mu  = rs_ * (1.0f/128.0f);
                float var = rq  * (1.0f/128.0f) - mu*mu;
                float rinv = rsqrtf(var + 1e-5f);
                float4 hv;
                hv.x = (v0-mu)*rinv*g4.x + lb4.x;
                hv.y = (v1-mu)*rinv*g4.y + lb4.y;
                hv.z = (v2-mu)*rinv*g4.z + lb4.z;
                hv.w = (v3-mu)*rinv*g4.w + lb4.w;
                *(float4*)&hout[(size_t)m*128 + colE] = hv;
            }
        }
    }
}

// ---------------- mma.sync flash attention (Q from qkv[0], K/V from frags) ----------------
__global__ __launch_bounds__(128) void attnT(const float* __restrict__ qkv,
                                             const u32* __restrict__ kvF,
                                             const int* __restrict__ mask,
                                             float* __restrict__ out) {
    __shared__ float Ms[512];
    int bh = blockIdx.y;
    int b = bh >> 3, h = bh & 7;
    int qbase = blockIdx.x * 128;
    int t = threadIdx.x, lane = t & 31, warp = t >> 5;
    int c2 = (lane & 3)*2;

    #pragma unroll
    for (int i = 0; i < 4; i++) {
        int key = i*128 + t;
        Ms[key] = mask[b*512 + key] ? 0.f : -1e30f;
    }
    __syncthreads();

    const u32* Kf = kvF + (size_t)bh * 8192;
    const u32* Vf = kvF + (size_t)(128 + bh) * 8192;

    const float qsc = 0.25f * 1.4426950408889634f;
    uint4 qh[2], ql[2];
    #pragma unroll
    for (int i = 0; i < 2; i++) {
        int r = qbase + warp*32 + i*16 + (lane >> 2);
        const float* b0p = qkv + (size_t)(b*512 + r)*128 + h*16;
        const float* b1p = b0p + 8*128;
        float2 fa = *(const float2*)(b0p + c2);
        float2 fc = *(const float2*)(b0p + c2 + 8);
        float2 fb = *(const float2*)(b1p + c2);
        float2 fd = *(const float2*)(b1p + c2 + 8);
        fa.x *= qsc; fa.y *= qsc; fb.x *= qsc; fb.y *= qsc;
        fc.x *= qsc; fc.y *= qsc; fd.x *= qsc; fd.y *= qsc;
        split2(fa.x, fa.y, qh[i].x, ql[i].x);
        split2(fb.x, fb.y, qh[i].y, ql[i].y);
        split2(fc.x, fc.y, qh[i].z, ql[i].z);
        split2(fd.x, fd.y, qh[i].w, ql[i].w);
    }

    float4 oAcc[2][2];
    float lAcc[2][2];
    #pragma unroll
    for (int i = 0; i < 2; i++) {
        oAcc[i][0] = make_float4(0,0,0,0);
        oAcc[i][1] = make_float4(0,0,0,0);
        lAcc[i][0] = 0.f; lAcc[i][1] = 0.f;
    }

    for (int kb = 0; kb < 8; kb++) {
        #pragma unroll
        for (int ktl = 0; ktl < 4; ktl++) {
            int nt0 = kb*8 + ktl*2;
            uint2 kh0 = *(const uint2*)&Kf[(nt0*32 + lane)*2];
            uint2 kh1 = *(const uint2*)&Kf[((nt0+1)*32 + lane)*2];
            uint2 kl0 = *(const uint2*)&Kf[4096 + (nt0*32 + lane)*2];
            uint2 kl1 = *(const uint2*)&Kf[4096 + ((nt0+1)*32 + lane)*2];

            float4 s[2][2];
            #pragma unroll
            for (int i = 0; i < 2; i++) {
                s[i][0] = make_float4(0,0,0,0);
                s[i][1] = make_float4(0,0,0,0);
                mma16816(s[i][0], qh[i], kh0);
                mma16816(s[i][0], ql[i], kh0);
                mma16816(s[i][0], qh[i], kl0);
                mma16816(s[i][1], qh[i], kh1);
                mma16816(s[i][1], ql[i], kh1);
                mma16816(s[i][1], qh[i], kl1);
            }

            int colb = nt0*8 + c2;
            float m00 = Ms[colb],     m01 = Ms[colb+1];
            float m10 = Ms[colb+8],   m11 = Ms[colb+9];

            uint4 pah[2], pal[2];
            #pragma unroll
            for (int i = 0; i < 2; i++) {
                float px0 = ex2f(s[i][0].x + m00);
                float py0 = ex2f(s[i][0].y + m01);
                float pz0 = ex2f(s[i][0].z + m00);
                float pw0 = ex2f(s[i][0].w + m01);
                float px1 = ex2f(s[i][1].x + m10);
                float py1 = ex2f(s[i][1].y + m11);
                float pz1 = ex2f(s[i][1].z + m10);
                float pw1 = ex2f(s[i][1].w + m11);
                lAcc[i][0] += px0 + py0 + px1 + py1;
                lAcc[i][1] += pz0 + pw0 + pz1 + pw1;
                split2(px0, py0, pah[i].x, pal[i].x);
                split2(pz0, pw0, pah[i].y, pal[i].y);
                split2(px1, py1, pah[i].z, pal[i].z);
                split2(pz1, pw1, pah[i].w, pal[i].w);
            }

            int ktg = kb*4 + ktl;
            uint2 vh0 = *(const uint2*)&Vf[((ktg*2 + 0)*32 + lane)*2];
            uint2 vh1 = *(const uint2*)&Vf[((ktg*2 + 1)*32 + lane)*2];
            uint2 vl0 = *(const uint2*)&Vf[4096 + ((ktg*2 + 0)*32 + lane)*2];
            uint2 vl1 = *(const uint2*)&Vf[4096 + ((ktg*2 + 1)*32 + lane)*2];
            #pragma unroll
            for (int i = 0; i < 2; i++) {
                mma16816(oAcc[i][0], pah[i], vh0);
                mma16816(oAcc[i][0], pal[i], vh0);
                mma16816(oAcc[i][0], pah[i], vl0);
                mma16816(oAcc[i][1], pah[i], vh1);
                mma16816(oAcc[i][1], pal[i], vh1);
                mma16816(oAcc[i][1], pah[i], vl1);
            }
        }
    }

    #pragma unroll
    for (int i = 0; i < 2; i++)
        #pragma unroll
        for (int j = 0; j < 2; j++) {
            lAcc[i][j] += __shfl_xor_sync(0xffffffffu, lAcc[i][j], 1);
            lAcc[i][j] += __shfl_xor_sync(0xffffffffu, lAcc[i][j], 2);
        }

    #pragma unroll
    for (int i = 0; i < 2; i++) {
        float inv0 = 1.f / lAcc[i][0];
        float inv1 = 1.f / lAcc[i][1];
        int r = qbase + warp*32 + i*16 + (lane >> 2);
        #pragma unroll
        for (int n = 0; n < 2; n++) {
            float* op = out + (size_t)(b*512 + r)*128 + h*16 + n*8 + c2;
            float2 lo = {oAcc[i][n].x * inv0, oAcc[i][n].y * inv0};
            float2 hi = {oAcc[i][n].z * inv1, oAcc[i][n].w * inv1};
            *(float2*)op = lo;
            *(float2*)(op + 8*128) = hi;
        }
    }
}

// ---------------- launch ----------------
extern "C" void kernel_launch(void* const* d_in, const int* in_sizes, int n_in,
                              void* d_out, int out_size) {
    const float* x     = (const float*)d_in[0];
    const int*   mask  = (const int*)  d_in[1];
    const float* ln_s  = (const float*)d_in[2];
    const float* ln_b  = (const float*)d_in[3];
    const float* dw_w  = (const float*)d_in[4];
    const float* dw_b  = (const float*)d_in[5];
    const float* pw_w  = (const float*)d_in[6];
    const float* pw_b  = (const float*)d_in[7];
    const float* Wq    = (const float*)d_in[8];
    const float* Wk    = (const float*)d_in[9];
    const float* Wv    = (const float*)d_in[10];
    const float* Wo    = (const float*)d_in[11];
    const float* ab    = (const float*)d_in[12];
    const float* f1w   = (const float*)d_in[13];
    const float* f1b   = (const float*)d_in[14];
    const float* f2w   = (const float*)d_in[15];
    const float* f2b   = (const float*)d_in[16];
    float* out = (float*)d_out;

    float *hA, *hB, *aP, *qkvP;
    u32 *wBP, *kvFP;
    cudaGetSymbolAddress((void**)&hA,   g_h);
    cudaGetSymbolAddress((void**)&hB,   g_h2);
    cudaGetSymbolAddress((void**)&aP,   g_a);
    cudaGetSymbolAddress((void**)&qkvP, g_qkv);
    cudaGetSymbolAddress((void**)&wBP,  g_wB);
    cudaGetSymbolAddress((void**)&kvFP, g_kvF);

    const int GSMEM = (16384 + 4224) * 4;       // 82432 B -> 2 blocks/SM

    auto gConv = gemmT<true,  false, 1, true,  true,  true,  false>;
    auto gQKV  = gemmT<false, true,  2, false, false, false, true>;
    auto gWo   = gemmT<false, false, 2, false, true,  true,  false>;
    auto gF1   = gemmT<false, false, 1, true,  false, false, false>;
    auto gF2   = gemmT<false, false, 1, false, true,  false, false>;
    cudaFuncSetAttribute(gConv, cudaFuncAttributeMaxDynamicSharedMemorySize, GSMEM);
    cudaFuncSetAttribute(gQKV,  cudaFuncAttributeMaxDynamicSharedMemorySize, GSMEM);
    cudaFuncSetAttribute(gWo,   cudaFuncAttributeMaxDynamicSharedMemorySize, GSMEM);
    cudaFuncSetAttribute(gF1,   cudaFuncAttributeMaxDynamicSharedMemorySize, GSMEM);
    cudaFuncSetAttribute(gF2,   cudaFuncAttributeMaxDynamicSharedMemorySize, GSMEM);

    prep_weights<<<640, 256>>>(Wq, Wk, Wv, pw_w, f1w, f2w, Wo, wBP);
    addpos_ln<<<128, 512>>>(x, out, hA, ln_s, ln_b);

    float* hin = hA; float* hob = hB;
    for (int i = 0; i < 4; i++) {
        gConv<<<256, 256, GSMEM>>>(hin, wBP + (size_t)(3+i)*16384, pw_b + i*128, out, out, hob,
                                   ln_s + (i+1)*128, ln_b + (i+1)*128,
                                   dw_w + i*896, dw_b + i*128, nullptr);
        float* tmp = hin; hin = hob; hob = tmp;
    }
    // hin holds LN[4](out)
    gQKV<<<dim3(256,3), 256, GSMEM>>>(hin, wBP, ab, nullptr, qkvP, nullptr,
                                      nullptr, nullptr, nullptr, nullptr, kvFP);
    attnT<<<dim3(4,128), 128>>>(qkvP, kvFP, mask, aP);
    gWo<<<256, 256, GSMEM>>>(aP, wBP + (size_t)9*16384, ab, out, out, hob,
                             ln_s + 5*128, ln_b + 5*128, nullptr, nullptr, nullptr);
    gF1<<<256, 256, GSMEM>>>(hob, wBP + (size_t)7*16384, f1b, nullptr, aP, nullptr,
                             nullptr, nullptr, nullptr, nullptr, nullptr);
    gF2<<<256, 256, GSMEM>>>(aP, wBP + (size_t)8*16384, f2b, out, out, nullptr,
                             nullptr, nullptr, nullptr, nullptr, nullptr);
}

// round 17
// speedup vs baseline: 1.9935x; 1.1797x over previous
#include <cuda_runtime.h>
#include <cuda_fp16.h>
#include <math.h>

#define TOKS 8192
#define ELEMS 1048576
typedef unsigned long long ull;
typedef unsigned int u32;
typedef unsigned short u16;

// ---------------- scratch ----------------
__device__ float g_h[ELEMS];
__device__ float g_h2[ELEMS];
__device__ float g_a[ELEMS];
__device__ float g_qkv[3*ELEMS];
__device__ u32 g_wB[10*16384];      // weights in B-frag order, fp16 hi/lo split
__device__ u32 g_kvF[2*128*8192];   // K,V frags per (b,h), fp16 hi/lo

// ---------------- helpers ----------------
__device__ __forceinline__ float ex2f(float x) {
    float r; asm("ex2.approx.f32 %0, %1;" : "=f"(r) : "f"(x)); return r;
}
// pack two f32 -> f16x2: low half = f0, high half = f1
__device__ __forceinline__ u32 pack_h2(float f0, float f1) {
    u32 r; asm("cvt.rn.f16x2.f32 %0, %1, %2;" : "=r"(r) : "f"(f1), "f"(f0)); return r;
}
__device__ __forceinline__ float h2f(u16 u) {
    return __half2float(__ushort_as_half(u));
}
__device__ __forceinline__ void split2h(float f0, float f1, u32& hi, u32& lo) {
    hi = pack_h2(f0, f1);
    float b0 = h2f((u16)(hi & 0xFFFFu));
    float b1 = h2f((u16)(hi >> 16));
    lo = pack_h2(f0 - b0, f1 - b1);
}
__device__ __forceinline__ void mma16816h(float4& c, const uint4& a, const uint2& b) {
    asm("mma.sync.aligned.m16n8k16.row.col.f32.f16.f16.f32 "
        "{%0,%1,%2,%3}, {%4,%5,%6,%7}, {%8,%9}, {%0,%1,%2,%3};"
        : "+f"(c.x), "+f"(c.y), "+f"(c.z), "+f"(c.w)
        : "r"(a.x), "r"(a.y), "r"(a.z), "r"(a.w), "r"(b.x), "r"(b.y));
}
__device__ __forceinline__ void cpasync16(u32 saddr, const void* g) {
    asm volatile("cp.async.cg.shared.global [%0], [%1], 16;" :: "r"(saddr), "l"(g));
}

// ---------------- weight prep: fp16 hi/lo B-frags ----------------
__global__ void prep_weights(const float* __restrict__ Wq, const float* __restrict__ Wk,
                             const float* __restrict__ Wv, const float* __restrict__ pw,
                             const float* __restrict__ f1, const float* __restrict__ f2,
                             const float* __restrict__ Wo, u32* __restrict__ wB) {
    int idx = blockIdx.x*256 + threadIdx.x;          // 10*16384
    if (idx >= 10*16384) return;
    int j = idx >> 14, r = idx & 16383;
    int k = r >> 7, n = r & 127;
    float v;
    if (j < 3) {
        const float* W = (j==0) ? Wq : (j==1) ? Wk : Wv;   // (H,128,16)
        v = W[(n>>4)*2048 + k*16 + (n&15)];
    } else if (j < 7) {
        v = pw[(j-3)*16384 + n*128 + k];
    } else if (j < 9) {
        const float* W = (j==7) ? f1 : f2;
        v = W[n*128 + k];
    } else {
        v = Wo[k*128 + n];
    }
    __half hh = __float2half_rn(v);
    __half ll = __float2half_rn(v - __half2float(hh));
    u16 h = __half_as_ushort(hh);
    u16 l = __half_as_ushort(ll);
    int kt = k >> 4, kk = k & 15;
    int reg = kk >> 3, tig = (kk & 7) >> 1, bb = kk & 1;
    int nt = n >> 3, lane = (n & 7)*4 + tig;
    u16* w16 = (u16*)(wB + (size_t)j*16384);
    int i32h = ((kt*16 + nt)*32 + lane)*2 + reg;
    int i32l = (((8 + kt)*16 + nt)*32 + lane)*2 + reg;
    w16[i32h*2 + bb] = h;
    w16[i32l*2 + bb] = l;
}

// ---------------- addpos + LN0 ----------------
__global__ __launch_bounds__(512) void addpos_ln(const float* __restrict__ x,
                                                 float* __restrict__ out, float* __restrict__ hout,
                                                 const float* __restrict__ lnS,
                                                 const float* __restrict__ lnB) {
    int m0 = blockIdx.x * 64;
    int lane = threadIdx.x & 31, warp = threadIdx.x >> 5;
    int col = lane * 4;
    const float inc = 0.14619588050756158f;   // log(10000)/63
    float4 g4 = *(const float4*)&lnS[col];
    float4 b4 = *(const float4*)&lnB[col];
    #pragma unroll
    for (int i = 0; i < 4; i++) {
        int m = m0 + warp*4 + i;
        int s = m & 511;
        float4 xv = *(const float4*)&x[m*128 + col];
        float v[4] = {xv.x, xv.y, xv.z, xv.w};
        #pragma unroll
        for (int jj = 0; jj < 4; jj++) {
            int d = col + jj;
            int dd = d & 63;
            float a = (float)s * expf(-inc*(float)dd);
            v[jj] += (d < 64) ? sinf(a) : cosf(a);
        }
        float rs_ = v[0]+v[1]+v[2]+v[3];
        float rq  = v[0]*v[0]+v[1]*v[1]+v[2]*v[2]+v[3]*v[3];
        #pragma unroll
        for (int o = 16; o > 0; o >>= 1) {
            rs_ += __shfl_xor_sync(0xffffffffu, rs_, o);
            rq  += __shfl_xor_sync(0xffffffffu, rq,  o);
        }
        float mu  = rs_ * (1.0f/128.0f);
        float var = rq  * (1.0f/128.0f) - mu*mu;
        float rinv = rsqrtf(var + 1e-5f);
        float4 ov = {v[0], v[1], v[2], v[3]};
        *(float4*)&out[m*128 + col] = ov;
        float4 hv;
        hv.x = (v[0]-mu)*rinv*g4.x + b4.x;
        hv.y = (v[1]-mu)*rinv*g4.y + b4.y;
        hv.z = (v[2]-mu)*rinv*g4.z + b4.z;
        hv.w = (v[3]-mu)*rinv*g4.w + b4.w;
        *(float4*)&hout[m*128 + col] = hv;
    }
}

// ---------------- tensor-core GEMM: 32xM tile, K=128, N=128, 256 thr ----------------
// A single-fp16 (one plane, 8KB); B fp16 hi/lo (64KB) via cp.async.
template<bool DW, bool MULTI, int BIASM, bool RELU, bool RES, bool LN, bool KVF>
__global__ __launch_bounds__(256) void gemmT(
    const float* __restrict__ A, const u32* __restrict__ Wf,
    const float* __restrict__ bias, const float* __restrict__ res,
    float* __restrict__ out, float* __restrict__ hout,
    const float* __restrict__ lnS, const float* __restrict__ lnB,
    const float* __restrict__ dww, const float* __restrict__ dwb,
    u32* __restrict__ kvF)
{
    extern __shared__ u32 smu[];
    u32* B32 = smu;                       // 16384 u32 (64 KB)
    u32* A32 = smu + 16384;               // 2048 u32 (8 KB)
    float* Csm = (float*)(smu + 16384);   // 32 x 132 f32 (aliased with A32 region)
    if (MULTI) { Wf += blockIdx.y * 16384; out += (size_t)blockIdx.y * ELEMS; }

    int m0 = blockIdx.x * 32;
    int t = threadIdx.x, lane = t & 31, warp = t >> 5;

    {
        u32 sbase = (u32)__cvta_generic_to_shared(&B32[t*4]);
        const u32* gsrc = Wf + t*4;
        #pragma unroll
        for (int i = 0; i < 16; i++)
            cpasync16(sbase + i*4096, gsrc + i*1024);
        asm volatile("cp.async.commit_group;" ::: "memory");
    }

    // A producer (single fp16 plane)
    u16* A16 = (u16*)A32;
    if (DW) {
        int d = t & 127, q = t >> 7;
        float wr[7];
        #pragma unroll
        for (int kk = 0; kk < 7; kk++) wr[kk] = dww[d*7 + kk];
        float db = dwb[d];
        int kt = d >> 4;
        int tig = (d & 7) >> 1, bb = d & 1;
        int kreg2 = ((d & 15) >> 3) * 2;
        const float* hb = A + (size_t)(m0 & ~511) * 128;
        int sBase = (m0 & 511) + q*16;
        float hwin[22];
        #pragma unroll
        for (int jj = 0; jj < 22; jj++) {
            int s = sBase + jj - 3;
            hwin[jj] = (s >= 0 && s < 512) ? hb[s*128 + d] : 0.f;
        }
        #pragma unroll
        for (int i = 0; i < 16; i++) {
            float acc = db;
            #pragma unroll
            for (int kk = 0; kk < 7; kk++) acc += wr[kk] * hwin[i+kk];
            int ml = q*16 + i;
            int mt = ml >> 4, mm = ml & 15;
            int g = mm & 7, hi8 = mm >> 3;
            int reg = hi8 + kreg2;
            int ln2 = g*4 + tig;
            int ih = ((mt*8 + kt)*32 + ln2)*4 + reg;
            A16[ih*2 + bb] = __half_as_ushort(__float2half_rn(acc));
        }
    } else {
        #pragma unroll
        for (int i = 0; i < 4; i++) {
            int idx4 = i*256 + t;
            int m = idx4 >> 5;
            int k0 = (idx4 & 31) * 4;
            float4 v = *(const float4*)&A[(size_t)(m0 + m)*128 + k0];
            float vv[4] = {v.x, v.y, v.z, v.w};
            int mt = m >> 4, mm = m & 15;
            int g = mm & 7, hi8 = mm >> 3;
            int kt = k0 >> 4;
            #pragma unroll
            for (int j = 0; j < 4; j += 2) {
                int k = k0 + j;
                int tig = (k & 7) >> 1;
                int reg = hi8 + 2*((k & 15) >> 3);
                int ln2 = g*4 + tig;
                A32[((mt*8 + kt)*32 + ln2)*4 + reg] = pack_h2(vv[j], vv[j+1]);
            }
        }
    }
    asm volatile("cp.async.wait_group 0;" ::: "memory");
    __syncthreads();

    // mainloop: 8 mmas per kt (ah x bh, ah x bl)
    int wm = warp >> 2, wn = warp & 3;
    int nt0 = wn*4;
    float4 acc[4];
    #pragma unroll
    for (int j = 0; j < 4; j++) acc[j] = make_float4(0.f,0.f,0.f,0.f);

    #pragma unroll
    for (int kt = 0; kt < 8; kt++) {
        uint4 ah = *(const uint4*)&A32[((wm*8 + kt)*32 + lane)*4];
        uint2 bh[4], bl[4];
        #pragma unroll
        for (int j = 0; j < 4; j++) {
            bh[j] = *(const uint2*)&B32[((kt*16 + nt0+j)*32 + lane)*2];
            bl[j] = *(const uint2*)&B32[(((8+kt)*16 + nt0+j)*32 + lane)*2];
        }
        #pragma unroll
        for (int j = 0; j < 4; j++) {
            mma16816h(acc[j], ah, bh[j]);
            mma16816h(acc[j], ah, bl[j]);
        }
    }
    __syncthreads();

    #pragma unroll
    for (int j = 0; j < 4; j++) {
        int row = wm*16 + (lane >> 2);
        int col = (nt0+j)*8 + (lane & 3)*2;
        float2 lo = {acc[j].x, acc[j].y};
        float2 hi = {acc[j].z, acc[j].w};
        *(float2*)&Csm[row*132 + col]     = lo;
        *(float2*)&Csm[(row+8)*132 + col] = hi;
    }
    __syncthreads();

    int colE = lane*4;
    float4 bv = {0,0,0,0};
    if (BIASM == 1) bv = *(const float4*)&bias[colE];
    float bs = (BIASM == 2) ? bias[0] : 0.f;
    float4 g4 = {0,0,0,0}, lb4 = {0,0,0,0};
    if (LN) { g4 = *(const float4*)&lnS[colE]; lb4 = *(const float4*)&lnB[colE]; }

    float va[4][4];
    #pragma unroll
    for (int i = 0; i < 4; i++) {
        int row = warp*4 + i;
        int m = m0 + row;
        float4 c4 = *(const float4*)&Csm[row*132 + colE];
        float v[4] = {c4.x, c4.y, c4.z, c4.w};
        #pragma unroll
        for (int jj = 0; jj < 4; jj++) {
            float val = v[jj];
            if (BIASM == 1) val += ((const float*)&bv)[jj];
            if (BIASM == 2) val += bs;
            if (RELU) val = fmaxf(val, 0.f);
            v[jj] = val;
        }
        if (RES) {
            float4 r4 = *(const float4*)&res[(size_t)m*128 + colE];
            v[0] += r4.x; v[1] += r4.y; v[2] += r4.z; v[3] += r4.w;
        }
        va[i][0] = v[0]; va[i][1] = v[1]; va[i][2] = v[2]; va[i][3] = v[3];
    }

    if (KVF && blockIdx.y != 0) {
        int mat = blockIdx.y - 1;
        int b = m0 >> 9;
        int h = colE >> 4;
        u32* dst = kvF + ((size_t)(mat*128) + b*8 + h) * 8192;
        int ld0 = colE & 15;
        if (mat == 0) {
            #pragma unroll
            for (int i = 0; i < 4; i++) {
                int key = (m0 & 511) + warp*4 + i;
                int nt = key >> 3, laneb = (key & 7)*4;
                int dp0 = ld0 >> 1;
                u32 hi, lo;
                split2h(va[i][0], va[i][1], hi, lo);
                int idx = (nt*32 + laneb + (dp0 & 3))*2 + (dp0 >> 2);
                dst[idx] = hi; dst[4096 + idx] = lo;
                int dp1 = dp0 + 1;
                split2h(va[i][2], va[i][3], hi, lo);
                idx = (nt*32 + laneb + (dp1 & 3))*2 + (dp1 >> 2);
                dst[idx] = hi; dst[4096 + idx] = lo;
            }
        } else {
            #pragma unroll
            for (int p = 0; p < 2; p++) {
                int key0 = (m0 & 511) + warp*4 + p*2;
                int kt = key0 >> 4, tig = (key0 >> 1) & 3, reg = (key0 & 15) >> 3;
                #pragma unroll
                for (int e = 0; e < 4; e++) {
                    int ld = ld0 + e;
                    int nt = ld >> 3, nn = ld & 7;
                    u32 hi, lo;
                    split2h(va[p*2][e], va[p*2+1][e], hi, lo);
                    int idx = ((kt*2 + nt)*32 + nn*4 + tig)*2 + reg;
                    dst[idx] = hi; dst[4096 + idx] = lo;
                }
            }
        }
    } else {
        #pragma unroll
        for (int i = 0; i < 4; i++) {
            int m = m0 + warp*4 + i;
            float4 ov = {va[i][0], va[i][1], va[i][2], va[i][3]};
            *(float4*)&out[(size_t)m*128 + colE] = ov;
            if (LN) {
                float v0 = va[i][0], v1 = va[i][1], v2 = va[i][2], v3 = va[i][3];
                float rs_ = v0+v1+v2+v3;
                float rq  = v0*v0+v1*v1+v2*v2+v3*v3;
                #pragma unroll
                for (int o = 16; o > 0; o >>= 1) {
                    rs_ += __shfl_xor_sync(0xffffffffu, rs_, o);
                    rq  += __shfl_xor_sync(0xffffffffu, rq,  o);
                }
                float mu  = rs_ * (1.0f/128.0f);
                float var = rq  * (1.0f/128.0f) - mu*mu;
                float rinv = rsqrtf(var + 1e-5f);
                float4 hv;
                hv.x = (v0-mu)*rinv*g4.x + lb4.x;
                hv.y = (v1-mu)*rinv*g4.y + lb4.y;
                hv.z = (v2-mu)*rinv*g4.z + lb4.z;
                hv.w = (v3-mu)*rinv*g4.w + lb4.w;
                *(float4*)&hout[(size_t)m*128 + colE] = hv;
            }
        }
    }
}

// ---------------- fp16 flash attention ----------------
__global__ __launch_bounds__(128) void attnT(const float* __restrict__ qkv,
                                             const u32* __restrict__ kvF,
                                             const int* __restrict__ mask,
                                             float* __restrict__ out) {
    __shared__ float Ms[512];
    int bh = blockIdx.y;
    int b = bh >> 3, h = bh & 7;
    int qbase = blockIdx.x * 128;
    int t = threadIdx.x, lane = t & 31, warp = t >> 5;
    int c2 = (lane & 3)*2;

    #pragma unroll
    for (int i = 0; i < 4; i++) {
        int key = i*128 + t;
        Ms[key] = mask[b*512 + key] ? 0.f : -1e30f;
    }
    __syncthreads();

    const u32* Kf = kvF + (size_t)bh * 8192;
    const u32* Vf = kvF + (size_t)(128 + bh) * 8192;

    const float qsc = 0.25f * 1.4426950408889634f;
    uint4 qh[2];
    #pragma unroll
    for (int i = 0; i < 2; i++) {
        int r = qbase + warp*32 + i*16 + (lane >> 2);
        const float* b0p = qkv + (size_t)(b*512 + r)*128 + h*16;
        const float* b1p = b0p + 8*128;
        float2 fa = *(const float2*)(b0p + c2);
        float2 fc = *(const float2*)(b0p + c2 + 8);
        float2 fb = *(const float2*)(b1p + c2);
        float2 fd = *(const float2*)(b1p + c2 + 8);
        qh[i].x = pack_h2(fa.x*qsc, fa.y*qsc);
        qh[i].y = pack_h2(fb.x*qsc, fb.y*qsc);
        qh[i].z = pack_h2(fc.x*qsc, fc.y*qsc);
        qh[i].w = pack_h2(fd.x*qsc, fd.y*qsc);
    }

    float4 oAcc[2][2];
    float lAcc[2][2];
    #pragma unroll
    for (int i = 0; i < 2; i++) {
        oAcc[i][0] = make_float4(0,0,0,0);
        oAcc[i][1] = make_float4(0,0,0,0);
        lAcc[i][0] = 0.f; lAcc[i][1] = 0.f;
    }

    for (int kb = 0; kb < 8; kb++) {
        #pragma unroll
        for (int ktl = 0; ktl < 4; ktl++) {
            int nt0 = kb*8 + ktl*2;
            uint2 kh0 = *(const uint2*)&Kf[(nt0*32 + lane)*2];
            uint2 kh1 = *(const uint2*)&Kf[((nt0+1)*32 + lane)*2];
            uint2 kl0 = *(const uint2*)&Kf[4096 + (nt0*32 + lane)*2];
            uint2 kl1 = *(const uint2*)&Kf[4096 + ((nt0+1)*32 + lane)*2];

            float4 s[2][2];
            #pragma unroll
            for (int i = 0; i < 2; i++) {
                s[i][0] = make_float4(0,0,0,0);
                s[i][1] = make_float4(0,0,0,0);
                mma16816h(s[i][0], qh[i], kh0);
                mma16816h(s[i][0], qh[i], kl0);
                mma16816h(s[i][1], qh[i], kh1);
                mma16816h(s[i][1], qh[i], kl1);
            }

            int colb = nt0*8 + c2;
            float m00 = Ms[colb],     m01 = Ms[colb+1];
            float m10 = Ms[colb+8],   m11 = Ms[colb+9];

            uint4 pah[2];
            #pragma unroll
            for (int i = 0; i < 2; i++) {
                float px0 = ex2f(s[i][0].x + m00);
                float py0 = ex2f(s[i][0].y + m01);
                float pz0 = ex2f(s[i][0].z + m00);
                float pw0 = ex2f(s[i][0].w + m01);
                float px1 = ex2f(s[i][1].x + m10);
                float py1 = ex2f(s[i][1].y + m11);
                float pz1 = ex2f(s[i][1].z + m10);
                float pw1 = ex2f(s[i][1].w + m11);
                lAcc[i][0] += px0 + py0 + px1 + py1;
                lAcc[i][1] += pz0 + pw0 + pz1 + pw1;
                pah[i].x = pack_h2(px0, py0);
                pah[i].y = pack_h2(pz0, pw0);
                pah[i].z = pack_h2(px1, py1);
                pah[i].w = pack_h2(pz1, pw1);
            }

            int ktg = kb*4 + ktl;
            uint2 vh0 = *(const uint2*)&Vf[((ktg*2 + 0)*32 + lane)*2];
            uint2 vh1 = *(const uint2*)&Vf[((ktg*2 + 1)*32 + lane)*2];
            uint2 vl0 = *(const uint2*)&Vf[4096 + ((ktg*2 + 0)*32 + lane)*2];
            uint2 vl1 = *(const uint2*)&Vf[4096 + ((ktg*2 + 1)*32 + lane)*2];
            #pragma unroll
            for (int i = 0; i < 2; i++) {
                mma16816h(oAcc[i][0], pah[i], vh0);
                mma16816h(oAcc[i][0], pah[i], vl0);
                mma16816h(oAcc[i][1], pah[i], vh1);
                mma16816h(oAcc[i][1], pah[i], vl1);
            }
        }
    }

    #pragma unroll
    for (int i = 0; i < 2; i++)
        #pragma unroll
        for (int j = 0; j < 2; j++) {
            lAcc[i][j] += __shfl_xor_sync(0xffffffffu, lAcc[i][j], 1);
            lAcc[i][j] += __shfl_xor_sync(0xffffffffu, lAcc[i][j], 2);
        }

    #pragma unroll
    for (int i = 0; i < 2; i++) {
        float inv0 = 1.f / lAcc[i][0];
        float inv1 = 1.f / lAcc[i][1];
        int r = qbase + warp*32 + i*16 + (lane >> 2);
        #pragma unroll
        for (int n = 0; n < 2; n++) {
            float* op = out + (size_t)(b*512 + r)*128 + h*16 + n*8 + c2;
            float2 lo = {oAcc[i][n].x * inv0, oAcc[i][n].y * inv0};
            float2 hi = {oAcc[i][n].z * inv1, oAcc[i][n].w * inv1};
            *(float2*)op = lo;
            *(float2*)(op + 8*128) = hi;
        }
    }
}

// ---------------- launch ----------------
extern "C" void kernel_launch(void* const* d_in, const int* in_sizes, int n_in,
                              void* d_out, int out_size) {
    const float* x     = (const float*)d_in[0];
    const int*   mask  = (const int*)  d_in[1];
    const float* ln_s  = (const float*)d_in[2];
    const float* ln_b  = (const float*)d_in[3];
    const float* dw_w  = (const float*)d_in[4];
    const float* dw_b  = (const float*)d_in[5];
    const float* pw_w  = (const float*)d_in[6];
    const float* pw_b  = (const float*)d_in[7];
    const float* Wq    = (const float*)d_in[8];
    const float* Wk    = (const float*)d_in[9];
    const float* Wv    = (const float*)d_in[10];
    const float* Wo    = (const float*)d_in[11];
    const float* ab    = (const float*)d_in[12];
    const float* f1w   = (const float*)d_in[13];
    const float* f1b   = (const float*)d_in[14];
    const float* f2w   = (const float*)d_in[15];
    const float* f2b   = (const float*)d_in[16];
    float* out = (float*)d_out;

    float *hA, *hB, *aP, *qkvP;
    u32 *wBP, *kvFP;
    cudaGetSymbolAddress((void**)&hA,   g_h);
    cudaGetSymbolAddress((void**)&hB,   g_h2);
    cudaGetSymbolAddress((void**)&aP,   g_a);
    cudaGetSymbolAddress((void**)&qkvP, g_qkv);
    cudaGetSymbolAddress((void**)&wBP,  g_wB);
    cudaGetSymbolAddress((void**)&kvFP, g_kvF);

    const int GSMEM = (16384 + 4224) * 4;       // 82432 B -> 2 blocks/SM

    auto gConv = gemmT<true,  false, 1, true,  true,  true,  false>;
    auto gQKV  = gemmT<false, true,  2, false, false, false, true>;
    auto gWo   = gemmT<false, false, 2, false, true,  true,  false>;
    auto gF1   = gemmT<false, false, 1, true,  false, false, false>;
    auto gF2   = gemmT<false, false, 1, false, true,  false, false>;
    cudaFuncSetAttribute(gConv, cudaFuncAttributeMaxDynamicSharedMemorySize, GSMEM);
    cudaFuncSetAttribute(gQKV,  cudaFuncAttributeMaxDynamicSharedMemorySize, GSMEM);
    cudaFuncSetAttribute(gWo,   cudaFuncAttributeMaxDynamicSharedMemorySize, GSMEM);
    cudaFuncSetAttribute(gF1,   cudaFuncAttributeMaxDynamicSharedMemorySize, GSMEM);
    cudaFuncSetAttribute(gF2,   cudaFuncAttributeMaxDynamicSharedMemorySize, GSMEM);

    prep_weights<<<640, 256>>>(Wq, Wk, Wv, pw_w, f1w, f2w, Wo, wBP);
    addpos_ln<<<128, 512>>>(x, out, hA, ln_s, ln_b);

    float* hin = hA; float* hob = hB;
    for (int i = 0; i < 4; i++) {
        gConv<<<256, 256, GSMEM>>>(hin, wBP + (size_t)(3+i)*16384, pw_b + i*128, out, out, hob,
                                   ln_s + (i+1)*128, ln_b + (i+1)*128,
                                   dw_w + i*896, dw_b + i*128, nullptr);
        float* tmp = hin; hin = hob; hob = tmp;
    }
    // hin holds LN[4](out)
    gQKV<<<dim3(256,3), 256, GSMEM>>>(hin, wBP, ab, nullptr, qkvP, nullptr,
                                      nullptr, nullptr, nullptr, nullptr, kvFP);
    attnT<<<dim3(4,128), 128>>>(qkvP, kvFP, mask, aP);
    gWo<<<256, 256, GSMEM>>>(aP, wBP + (size_t)9*16384, ab, out, out, hob,
                             ln_s + 5*128, ln_b + 5*128, nullptr, nullptr, nullptr);
    gF1<<<256, 256, GSMEM>>>(hob, wBP + (size_t)7*16384, f1b, nullptr, aP, nullptr,
                             nullptr, nullptr, nullptr, nullptr, nullptr);
    gF2<<<256, 256, GSMEM>>>(aP, wBP + (size_t)8*16384, f2b, out, out, nullptr,
                             nullptr, nullptr, nullptr, nullptr, nullptr);
}